// round 6
// baseline (speedup 1.0000x reference)
#include <cuda_runtime.h>
#include <math.h>

#define N_NODES 100000
#define N_EDGES 1280000
#define DIM 64

// ---------------------------------------------------------------------------
// Scratch (__device__ globals; allocation-free rule).
// g_agg is fully overwritten every call by agg_kernel -> no zeroing needed.
// g_cnt is zeroed at the start of every call by zero_cnt_kernel.
// ---------------------------------------------------------------------------
__device__ float g_agg[(size_t)N_NODES * DIM];     // 25.6 MB (normalized h)
__device__ int   g_cnt[N_NODES];                   // in-degree (histogram)
__device__ int   g_loc[N_NODES];                   // per-block-local excl scan
__device__ int   g_off[N_NODES];                   // CSR row starts
__device__ int   g_cur[N_NODES];                   // permute cursors
__device__ int   g_bsum[128];                      // scan block sums
__device__ int   g_bsum_sc[128];                   // scanned block sums
__device__ int2  g_edges[N_EDGES];                 // packed {src, w-bits}, 10.2 MB

#define SCAN_BLK 1024                               // elems per scan block
#define NB_SCAN ((N_NODES + SCAN_BLK - 1) / SCAN_BLK)   // 98

// ---------------------------------------------------------------------------
// 0: zero degree counters (int4-vectorized; N divisible by 4)
// ---------------------------------------------------------------------------
__global__ __launch_bounds__(256) void zero_cnt_kernel() {
    int i = blockIdx.x * blockDim.x + threadIdx.x;
    if (i < N_NODES / 4) ((int4*)g_cnt)[i] = make_int4(0, 0, 0, 0);
}

// ---------------------------------------------------------------------------
// 1: histogram of dst -> g_cnt
// ---------------------------------------------------------------------------
__global__ __launch_bounds__(256) void hist_kernel(const int* __restrict__ dst) {
    int e = blockIdx.x * blockDim.x + threadIdx.x;
    if (e < N_EDGES) atomicAdd(&g_cnt[__ldg(dst + e)], 1);
}

// ---------------------------------------------------------------------------
// 2a: per-block exclusive scan of g_cnt (1024 elems/block, 256 thr x 4)
// ---------------------------------------------------------------------------
__global__ __launch_bounds__(256) void scan1_kernel() {
    __shared__ int sh[256];
    const int tid  = threadIdx.x;
    const int base = blockIdx.x * SCAN_BLK + tid * 4;

    int v[4];
    #pragma unroll
    for (int j = 0; j < 4; j++)
        v[j] = (base + j < N_NODES) ? g_cnt[base + j] : 0;
    int tsum = v[0] + v[1] + v[2] + v[3];

    sh[tid] = tsum;
    #pragma unroll
    for (int off = 1; off < 256; off <<= 1) {
        __syncthreads();
        int add = (tid >= off) ? sh[tid - off] : 0;
        __syncthreads();
        sh[tid] += add;
    }
    __syncthreads();
    int excl = sh[tid] - tsum;                 // exclusive prefix of this thread

    int run = excl;
    #pragma unroll
    for (int j = 0; j < 4; j++) {
        if (base + j < N_NODES) g_loc[base + j] = run;
        run += v[j];
    }
    if (tid == 255) g_bsum[blockIdx.x] = sh[255];
}

// ---------------------------------------------------------------------------
// 2b: scan the 98 block sums (single block)
// ---------------------------------------------------------------------------
__global__ __launch_bounds__(128) void scan2_kernel() {
    __shared__ int sh[128];
    const int tid = threadIdx.x;
    int v = (tid < NB_SCAN) ? g_bsum[tid] : 0;
    sh[tid] = v;
    #pragma unroll
    for (int off = 1; off < 128; off <<= 1) {
        __syncthreads();
        int add = (tid >= off) ? sh[tid - off] : 0;
        __syncthreads();
        sh[tid] += add;
    }
    __syncthreads();
    if (tid < NB_SCAN) g_bsum_sc[tid] = sh[tid] - v;   // exclusive
}

// ---------------------------------------------------------------------------
// 2c: add block offsets -> g_off, and init cursors g_cur
// ---------------------------------------------------------------------------
__global__ __launch_bounds__(256) void scan3_kernel() {
    const int base = blockIdx.x * SCAN_BLK + threadIdx.x * 4;
    const int add  = g_bsum_sc[blockIdx.x];
    #pragma unroll
    for (int j = 0; j < 4; j++) {
        int i = base + j;
        if (i < N_NODES) {
            int o = g_loc[i] + add;
            g_off[i] = o;
            g_cur[i] = o;
        }
    }
}

// ---------------------------------------------------------------------------
// 3: permute edges into CSR order, packed as int2{src, w-bits}
// ---------------------------------------------------------------------------
__global__ __launch_bounds__(256) void permute_kernel(
    const float* __restrict__ w,
    const int*   __restrict__ src,
    const int*   __restrict__ dst)
{
    int e = blockIdx.x * blockDim.x + threadIdx.x;
    if (e >= N_EDGES) return;
    int d = __ldg(dst + e);
    int pos = atomicAdd(&g_cur[d], 1);
    g_edges[pos] = make_int2(__ldg(src + e), __float_as_int(__ldg(w + e)));
}

// ---------------------------------------------------------------------------
// 4: aggregate + normalize (gather-only, no atomics).
// 4 threads per node; each owns 16 feature slots (float4 at lane, lane+4, +8, +12).
// 2-edge unrolled inner loop -> 8 outstanding LDG.128 per thread.
// ---------------------------------------------------------------------------
__global__ __launch_bounds__(256) void agg_kernel(const float* __restrict__ feat) {
    const unsigned t    = blockIdx.x * blockDim.x + threadIdx.x;
    const unsigned n    = t >> 2;
    const unsigned lane = t & 3;
    if (n >= N_NODES) return;

    const int beg = g_off[n];
    const int deg = g_cnt[n];
    const int2* ep = g_edges + beg;

    float4 a0 = make_float4(0.f, 0.f, 0.f, 0.f);
    float4 a1 = a0, a2 = a0, a3 = a0;

    int i = 0;
    for (; i + 2 <= deg; i += 2) {
        int2 e0 = __ldg(ep + i);
        int2 e1 = __ldg(ep + i + 1);
        const float4* p0 = (const float4*)(feat + (size_t)e0.x * DIM) + lane;
        const float4* p1 = (const float4*)(feat + (size_t)e1.x * DIM) + lane;
        float4 f00 = __ldg(p0);     float4 f01 = __ldg(p0 + 4);
        float4 f02 = __ldg(p0 + 8); float4 f03 = __ldg(p0 + 12);
        float4 f10 = __ldg(p1);     float4 f11 = __ldg(p1 + 4);
        float4 f12 = __ldg(p1 + 8); float4 f13 = __ldg(p1 + 12);
        float w0 = __int_as_float(e0.y);
        float w1 = __int_as_float(e1.y);
        a0.x += f00.x * w0; a0.y += f00.y * w0; a0.z += f00.z * w0; a0.w += f00.w * w0;
        a1.x += f01.x * w0; a1.y += f01.y * w0; a1.z += f01.z * w0; a1.w += f01.w * w0;
        a2.x += f02.x * w0; a2.y += f02.y * w0; a2.z += f02.z * w0; a2.w += f02.w * w0;
        a3.x += f03.x * w0; a3.y += f03.y * w0; a3.z += f03.z * w0; a3.w += f03.w * w0;
        a0.x += f10.x * w1; a0.y += f10.y * w1; a0.z += f10.z * w1; a0.w += f10.w * w1;
        a1.x += f11.x * w1; a1.y += f11.y * w1; a1.z += f11.z * w1; a1.w += f11.w * w1;
        a2.x += f12.x * w1; a2.y += f12.y * w1; a2.z += f12.z * w1; a2.w += f12.w * w1;
        a3.x += f13.x * w1; a3.y += f13.y * w1; a3.z += f13.z * w1; a3.w += f13.w * w1;
    }
    if (i < deg) {
        int2 e0 = __ldg(ep + i);
        const float4* p0 = (const float4*)(feat + (size_t)e0.x * DIM) + lane;
        float4 f00 = __ldg(p0);     float4 f01 = __ldg(p0 + 4);
        float4 f02 = __ldg(p0 + 8); float4 f03 = __ldg(p0 + 12);
        float w0 = __int_as_float(e0.y);
        a0.x += f00.x * w0; a0.y += f00.y * w0; a0.z += f00.z * w0; a0.w += f00.w * w0;
        a1.x += f01.x * w0; a1.y += f01.y * w0; a1.z += f01.z * w0; a1.w += f01.w * w0;
        a2.x += f02.x * w0; a2.y += f02.y * w0; a2.z += f02.z * w0; a2.w += f02.w * w0;
        a3.x += f03.x * w0; a3.y += f03.y * w0; a3.z += f03.z * w0; a3.w += f03.w * w0;
    }

    const float dinv = 1.0f / fmaxf((float)deg, 1.0f);
    float4* op = (float4*)(g_agg + (size_t)n * DIM) + lane;
    a0.x *= dinv; a0.y *= dinv; a0.z *= dinv; a0.w *= dinv;
    a1.x *= dinv; a1.y *= dinv; a1.z *= dinv; a1.w *= dinv;
    a2.x *= dinv; a2.y *= dinv; a2.z *= dinv; a2.w *= dinv;
    a3.x *= dinv; a3.y *= dinv; a3.z *= dinv; a3.w *= dinv;
    op[0]  = a0; op[4]  = a1; op[8]  = a2; op[12] = a3;
}

// ---------------------------------------------------------------------------
// 5: GEMM  out = g_agg @ W.   128 threads, tile 128 rows x 64 cols,
// 8x8 register blocking: per k-iter 64B LDS for 64 FMA -> FFMA-bound.
// ---------------------------------------------------------------------------
#define TROWS 128
#define HSTRIDE 132

__global__ __launch_bounds__(128) void gemm_kernel(
    const float* __restrict__ Wm,      // [64,64] row-major (k, c)
    float*       __restrict__ out)     // [N, 64]
{
    __shared__ float Wsh[DIM][DIM];          // 16 KB
    __shared__ float Hsh[DIM][HSTRIDE];      // [k][row], 33.8 KB

    const int tid   = threadIdx.x;
    const int rbase = blockIdx.x * TROWS;

    // Load W: 4096 floats / 128 threads = 8 float4 each.
    #pragma unroll
    for (int i = tid * 4; i < DIM * DIM; i += 128 * 4)
        *(float4*)(&Wsh[0][0] + i) = __ldg((const float4*)(Wm + i));

    // Load H tile transposed: 4 chunks of 32 rows; 4 threads/row.
    {
        const int lrow = tid >> 2;          // 0..31 within chunk
        const int lane = tid & 3;
        #pragma unroll
        for (int c = 0; c < 4; c++) {
            const int row = lrow + 32 * c;
            const int gr  = rbase + row;
            const float4* ap = (const float4*)(g_agg + (size_t)gr * DIM) + lane;
            #pragma unroll
            for (int q = 0; q < 4; q++) {
                float4 v = (gr < N_NODES) ? __ldg(ap + 4 * q)
                                          : make_float4(0.f, 0.f, 0.f, 0.f);
                const int k = lane * 4 + q * 16;
                Hsh[k + 0][row] = v.x;
                Hsh[k + 1][row] = v.y;
                Hsh[k + 2][row] = v.z;
                Hsh[k + 3][row] = v.w;
            }
        }
    }
    __syncthreads();

    // Compute: thread (ty,tx) owns rows 8ty..+7, cols 8tx..+7.
    const int ty = tid >> 3;       // 0..15
    const int tx = tid & 7;        // 0..7
    float acc[8][8] = {};

    #pragma unroll 4
    for (int k = 0; k < DIM; k++) {
        float4 av0 = *(const float4*)&Hsh[k][8 * ty];
        float4 av1 = *(const float4*)&Hsh[k][8 * ty + 4];
        float4 bv0 = *(const float4*)&Wsh[k][8 * tx];
        float4 bv1 = *(const float4*)&Wsh[k][8 * tx + 4];
        float ar[8] = {av0.x, av0.y, av0.z, av0.w, av1.x, av1.y, av1.z, av1.w};
        float br[8] = {bv0.x, bv0.y, bv0.z, bv0.w, bv1.x, bv1.y, bv1.z, bv1.w};
        #pragma unroll
        for (int i = 0; i < 8; i++)
            #pragma unroll
            for (int j = 0; j < 8; j++)
                acc[i][j] += ar[i] * br[j];
    }

    #pragma unroll
    for (int i = 0; i < 8; i++) {
        const int r = rbase + 8 * ty + i;
        if (r < N_NODES) {
            float4* po = (float4*)(out + (size_t)r * DIM + 8 * tx);
            po[0] = make_float4(acc[i][0], acc[i][1], acc[i][2], acc[i][3]);
            po[1] = make_float4(acc[i][4], acc[i][5], acc[i][6], acc[i][7]);
        }
    }
}

// ---------------------------------------------------------------------------
// kernel_launch: CSR build -> gather-aggregate -> GEMM.
// Inputs (metadata order): features, w, W, src, dst.  Output: float [N, 64].
// ---------------------------------------------------------------------------
extern "C" void kernel_launch(void* const* d_in, const int* in_sizes, int n_in,
                              void* d_out, int out_size)
{
    const float* feat = (const float*)d_in[0];
    const float* w    = (const float*)d_in[1];
    const float* Wm   = (const float*)d_in[2];
    const int*   src  = (const int*)d_in[3];
    const int*   dst  = (const int*)d_in[4];
    float*       out  = (float*)d_out;

    zero_cnt_kernel<<<(N_NODES / 4 + 255) / 256, 256>>>();
    hist_kernel<<<(N_EDGES + 255) / 256, 256>>>(dst);
    scan1_kernel<<<NB_SCAN, 256>>>();
    scan2_kernel<<<1, 128>>>();
    scan3_kernel<<<NB_SCAN, 256>>>();
    permute_kernel<<<(N_EDGES + 255) / 256, 256>>>(w, src, dst);
    agg_kernel<<<(N_NODES * 4 + 255) / 256, 256>>>(feat);
    gemm_kernel<<<(N_NODES + TROWS - 1) / TROWS, 128>>>(Wm, out);
}

// round 8
// speedup vs baseline: 1.1092x; 1.1092x over previous
#include <cuda_runtime.h>
#include <math.h>

#define N_NODES 100000
#define N_EDGES 1280000
#define DIM 64

// Scratch (allocation-free rule: __device__ globals, zero-initialized at load).
// gemm kernel re-zeroes both arrays each call, so no separate zero pass ever.
__device__ float g_agg[(size_t)N_NODES * DIM];   // 25.6 MB
__device__ float g_deg[N_NODES];

// ---------------------------------------------------------------------------
// Kernel 1: edge scatter.  4 threads per edge; each thread gathers 4 float4
// (MLP=4), scales by w, fires 4 vector REDs.  Per warp: 8 edges with 12 LSU
// instructions; every access is a full-sector 64B chunk.
// ---------------------------------------------------------------------------
__global__ __launch_bounds__(256) void edge_kernel(
    const float* __restrict__ feat,
    const float* __restrict__ w,
    const int*   __restrict__ src,
    const int*   __restrict__ dst)
{
    unsigned t    = blockIdx.x * blockDim.x + threadIdx.x;
    unsigned e    = t >> 2;
    unsigned lane = t & 3;
    if (e >= N_EDGES) return;

    int   s  = __ldg(src + e);
    int   d  = __ldg(dst + e);
    float we = __ldg(w + e);

    const float4* fp = (const float4*)(feat + (size_t)s * DIM) + lane;
    float4 f[4];
    #pragma unroll
    for (int q = 0; q < 4; q++) f[q] = __ldg(fp + 4 * q);

    float* base = g_agg + (size_t)d * DIM + lane * 4;
    #pragma unroll
    for (int q = 0; q < 4; q++) {
        float x = f[q].x * we, y = f[q].y * we, z = f[q].z * we, v = f[q].w * we;
        asm volatile("red.global.add.v4.f32 [%0], {%1,%2,%3,%4};"
                     :: "l"(base + q * 16), "f"(x), "f"(y), "f"(z), "f"(v)
                     : "memory");
    }

    if (lane == 0) atomicAdd(g_deg + d, 1.0f);   // RED (result unused)
}

// ---------------------------------------------------------------------------
// Kernel 2: fused normalize + GEMM + scratch reset.
//   out[r] = (agg[r] * dinv[r]) @ W
// Block: 256 rows x 64 cols, 256 threads, 8x8 register tiles.
// Per k-iter per thread: 64B LDS feeding 64 FMA -> FFMA-bound (LDS at ~50%).
// Hsh stored transposed [k][row] so the A operand is 2x LDS.128.
// Loader zeroes the g_agg float4s it alone read; g_deg reset after the sync.
// ---------------------------------------------------------------------------
#define TROWS 256
#define HSTRIDE 260   // 256 + 4 pad, keeps 16B alignment of [k][8*ty]

__global__ __launch_bounds__(256) void gemm_kernel(
    const float* __restrict__ Wm,      // [64,64] row-major (k, c)
    float*       __restrict__ out)     // [N, 64]
{
    __shared__ float Wsh[DIM][DIM];          // 16 KB
    __shared__ float Hsh[DIM][HSTRIDE];      // [k][row], 66.6 KB

    const int tid   = threadIdx.x;
    const int rbase = blockIdx.x * TROWS;

    // Load W cooperatively: 4096 floats / 256 threads = 4 float4 each.
    #pragma unroll
    for (int i = tid * 4; i < DIM * DIM; i += 256 * 4)
        *(float4*)(&Wsh[0][0] + i) = __ldg((const float4*)(Wm + i));

    // Load H tile transposed with degree normalization; reset scratch.
    // 4 threads per row, 64 rows per chunk, 4 chunks.  Warp = 8 rows x 4
    // lanes -> every LDG/STG is a contiguous 64B-per-row full-sector access.
    {
        const int lrow = tid >> 2;          // 0..63
        const int lane = tid & 3;           // float4 slots: lane, +4, +8, +12
        const float4 z4 = make_float4(0.f, 0.f, 0.f, 0.f);
        #pragma unroll
        for (int c = 0; c < 4; c++) {
            const int row   = lrow + 64 * c;
            const int gr    = rbase + row;
            const bool valid = (gr < N_NODES);
            float dinv = 0.f;
            if (valid) dinv = 1.0f / fmaxf(g_deg[gr], 1.0f);
            float4* ap = (float4*)(g_agg + (size_t)gr * DIM) + lane;
            #pragma unroll
            for (int q = 0; q < 4; q++) {
                float4 v = valid ? ap[4 * q] : z4;
                const int k = lane * 4 + q * 16;
                Hsh[k + 0][row] = v.x * dinv;
                Hsh[k + 1][row] = v.y * dinv;
                Hsh[k + 2][row] = v.z * dinv;
                Hsh[k + 3][row] = v.w * dinv;
                if (valid) ap[4 * q] = z4;          // sole reader: reset now
            }
        }
    }
    __syncthreads();

    // Reset degree for next call (all readers are past the sync).
    {
        const int gr = rbase + tid;
        if (gr < N_NODES) g_deg[gr] = 0.f;
    }

    // Compute: thread (ty,tx) owns rows 8ty..+7, cols 8tx..+7.
    const int ty = tid >> 3;       // 0..31
    const int tx = tid & 7;        // 0..7
    float acc[8][8] = {};

    #pragma unroll 4
    for (int k = 0; k < DIM; k++) {
        float4 av0 = *(const float4*)&Hsh[k][8 * ty];
        float4 av1 = *(const float4*)&Hsh[k][8 * ty + 4];
        float4 bv0 = *(const float4*)&Wsh[k][8 * tx];
        float4 bv1 = *(const float4*)&Wsh[k][8 * tx + 4];
        float ar[8] = {av0.x, av0.y, av0.z, av0.w, av1.x, av1.y, av1.z, av1.w};
        float br[8] = {bv0.x, bv0.y, bv0.z, bv0.w, bv1.x, bv1.y, bv1.z, bv1.w};
        #pragma unroll
        for (int i = 0; i < 8; i++)
            #pragma unroll
            for (int j = 0; j < 8; j++)
                acc[i][j] += ar[i] * br[j];
    }

    #pragma unroll
    for (int i = 0; i < 8; i++) {
        const int r = rbase + 8 * ty + i;
        if (r < N_NODES) {
            float4* po = (float4*)(out + (size_t)r * DIM + 8 * tx);
            po[0] = make_float4(acc[i][0], acc[i][1], acc[i][2], acc[i][3]);
            po[1] = make_float4(acc[i][4], acc[i][5], acc[i][6], acc[i][7]);
        }
    }
}

// ---------------------------------------------------------------------------
// kernel_launch: edge scatter -> fused normalize+GEMM+reset.
// Scratch starts zeroed (static zero-init on call 1; gemm resets it for the
// next call).  Identical work every call -> deterministic & graph-capturable.
// Inputs (metadata order): features, w, W, src, dst.  Output: float [N, 64].
// ---------------------------------------------------------------------------
extern "C" void kernel_launch(void* const* d_in, const int* in_sizes, int n_in,
                              void* d_out, int out_size)
{
    const float* feat = (const float*)d_in[0];
    const float* w    = (const float*)d_in[1];
    const float* Wm   = (const float*)d_in[2];
    const int*   src  = (const int*)d_in[3];
    const int*   dst  = (const int*)d_in[4];
    float*       out  = (float*)d_out;

    {
        long long threads = (long long)N_EDGES * 4;
        int grid = (int)((threads + 255) / 256);
        edge_kernel<<<grid, 256>>>(feat, w, src, dst);
    }
    {
        int grid = (N_NODES + TROWS - 1) / TROWS;
        gemm_kernel<<<grid, 256>>>(Wm, out);
    }
}